// round 10
// baseline (speedup 1.0000x reference)
#include <cuda_runtime.h>
#include <cstdint>

// Round 10: single flat pass, decoupled-lookback style.
//  - 8192 perfectly balanced 2048-elem chunks (one block each, zero skew)
//  - partial sum(exp) published to g_sum[seg] via warp-aggregated RED
//  - completion counted in g_cnt[seg] (expected count known analytically)
//  - block spins for its segments' lse, then writes FROM REGISTERS
//  -> logits read once, out written once; no second read pass.

#define T    128
#define CH   2048
#define CH4  (CH / 4)       // 512 float4 per chunk
#define QPT  (CH4 / T)      // 4 float4 per thread
#define TBL  96
#define MAXSEG 16384

__device__ float g_sum[MAXSEG];
__device__ int   g_cnt[MAXSEG];

__global__ void zero_kernel(int nseg) {
    int i = blockIdx.x * blockDim.x + threadIdx.x;
    if (i < nseg) { g_sum[i] = 0.0f; g_cnt[i] = 0; }
}

__device__ __forceinline__ float warp_sum(float v) {
    #pragma unroll
    for (int o = 16; o > 0; o >>= 1)
        v += __shfl_xor_sync(0xFFFFFFFFu, v, o);
    return v;
}

// segment end for table slot k (global fallback past TBL)
__device__ __forceinline__ int seg_end(const int* __restrict__ prefix, int nseg,
                                       int s0, const int* s_end_sm, int k) {
    if (k < TBL) return s_end_sm[k];
    int sj = s0 + k;
    return (sj < nseg) ? __ldg(&prefix[sj]) : 0x7FFFFFFF;
}

__device__ __forceinline__ float spin_lse(int j, int startj, int endj) {
    int expc = (endj - 1) / CH - startj / CH + 1;
    volatile int* pc = &g_cnt[j];
    while (*pc != expc) __nanosleep(64);
    __threadfence();
    return __logf(*(volatile float*)&g_sum[j]);
}

__global__ void __launch_bounds__(T)
jls_kernel(const float* __restrict__ logits,
           const int* __restrict__ prefix,
           float* __restrict__ out,
           int total, int nseg) {
    __shared__ int   s_end[TBL];
    __shared__ float s_lse[TBL];

    const int tid   = threadIdx.x;
    const int lane  = tid & 31;
    const int chunk = blockIdx.x;
    const int cbeg  = chunk * CH;
    const int cend  = min(cbeg + CH, total);
    if (cbeg >= total) return;

    // s0 = segment owning cbeg (first j with prefix[j] > cbeg)
    int lo = 0, hi = nseg;
    while (lo < hi) {
        int mid = (lo + hi) >> 1;
        if (__ldg(&prefix[mid]) <= cbeg) lo = mid + 1; else hi = mid;
    }
    const int s0 = lo;
    const int start0 = (s0 == 0) ? 0 : __ldg(&prefix[s0 - 1]);

    if (tid < TBL) {
        int sj = s0 + tid;
        s_end[tid] = (sj < nseg) ? __ldg(&prefix[sj]) : 0x7FFFFFFF;
    }
    __syncthreads();

    // nover = slots covering [cbeg, cend)
    int nover = 1;
    { int k = 0; while (seg_end(prefix, nseg, s0, s_end, k) < cend) k++; nover = k + 1; }

    // ---- batched register load (MLP = QPT per thread) ----
    const float4* __restrict__ logits4 = (const float4*)logits;
    float4 v[QPT];
    #pragma unroll
    for (int q = 0; q < QPT; q++) {
        int i4 = chunk * CH4 + q * T + tid;
        if (i4 * 4 < total) v[q] = __ldg(&logits4[i4]);
    }

    // ---- publish per-segment partial sum(exp) ----
    int k = 0;
    #pragma unroll
    for (int q = 0; q < QPT; q++) {
        int e = (chunk * CH4 + q * T + tid) * 4;
        bool valid = (e < total);
        if (valid) { while (e >= seg_end(prefix, nseg, s0, s_end, k)) k++; }
        int  ke    = valid ? seg_end(prefix, nseg, s0, s_end, k) : 0x7FFFFFFF;
        bool whole = valid && (e + 4 <= ke);

        float p = 0.0f;
        if (whole)
            p = __expf(v[q].x) + __expf(v[q].y) + __expf(v[q].z) + __expf(v[q].w);

        unsigned wb = __ballot_sync(0xFFFFFFFFu, whole);
        if (wb == 0xFFFFFFFFu) {
            unsigned peers = __match_any_sync(0xFFFFFFFFu, k);
            if (peers == 0xFFFFFFFFu) {                 // warp-uniform segment
                p = warp_sum(p);
                if (lane == 0) atomicAdd(&g_sum[s0 + k], p);
            } else {
                atomicAdd(&g_sum[s0 + k], p);
            }
        } else if (whole) {
            atomicAdd(&g_sum[s0 + k], p);
        } else if (valid) {                             // float4 split / tail
            int kk = k;
            float xs[4] = {v[q].x, v[q].y, v[q].z, v[q].w};
            #pragma unroll
            for (int t2 = 0; t2 < 4; t2++) {
                if (e + t2 < total) {
                    while (e + t2 >= seg_end(prefix, nseg, s0, s_end, kk)) kk++;
                    atomicAdd(&g_sum[s0 + kk], __expf(xs[t2]));
                }
            }
        }
    }

    __threadfence();      // sums globally visible before counts
    __syncthreads();

    // ---- completion counts: one per (chunk, nonempty overlapped segment) ----
    for (int kk = tid; kk < nover; kk += T) {
        int endk   = seg_end(prefix, nseg, s0, s_end, kk);
        int startk = (kk == 0) ? start0 : seg_end(prefix, nseg, s0, s_end, kk - 1);
        if (endk > startk) atomicAdd(&g_cnt[s0 + kk], 1);
    }

    // ---- spin for lse of our slots ----
    for (int kk = tid; kk < nover && kk < TBL; kk += T) {
        int endk   = s_end[kk];
        int startk = (kk == 0) ? start0 : s_end[kk - 1];
        if (endk > startk) s_lse[kk] = spin_lse(s0 + kk, startk, endk);
    }
    __syncthreads();

    // ---- write from registers ----
    k = 0;
    #pragma unroll
    for (int q = 0; q < QPT; q++) {
        int i4 = chunk * CH4 + q * T + tid;
        int e = i4 * 4;
        if (e >= total) break;
        while (e >= seg_end(prefix, nseg, s0, s_end, k)) k++;
        int ke = seg_end(prefix, nseg, s0, s_end, k);

        float4 r;
        if (e + 4 <= ke && k < TBL) {                   // common case
            float L = s_lse[k];
            r.x = v[q].x - L; r.y = v[q].y - L; r.z = v[q].z - L; r.w = v[q].w - L;
        } else {                                        // split or table overflow
            int kk = k;
            float xs[4] = {v[q].x, v[q].y, v[q].z, v[q].w};
            float rs[4] = {0, 0, 0, 0};
            #pragma unroll
            for (int t2 = 0; t2 < 4; t2++) {
                if (e + t2 < total) {
                    while (e + t2 >= seg_end(prefix, nseg, s0, s_end, kk)) kk++;
                    float L;
                    if (kk < TBL) {
                        L = s_lse[kk];
                    } else {
                        int endk   = seg_end(prefix, nseg, s0, s_end, kk);
                        int startk = seg_end(prefix, nseg, s0, s_end, kk - 1);
                        L = spin_lse(s0 + kk, startk, endk);
                    }
                    rs[t2] = xs[t2] - L;
                }
            }
            r.x = rs[0]; r.y = rs[1]; r.z = rs[2]; r.w = rs[3];
        }
        __stcs((float4*)&out[e], r);
    }
}

extern "C" void kernel_launch(void* const* d_in, const int* in_sizes, int n_in,
                              void* d_out, int out_size) {
    const float* logits     = (const float*)d_in[0];
    const int*   prefix_sum = (const int*)d_in[1];
    float*       out        = (float*)d_out;

    const int num_segs = in_sizes[1];
    const int total    = out_size;
    const int nchunks  = (total + CH - 1) / CH;

    zero_kernel<<<(num_segs + 255) / 256, 256>>>(num_segs);
    jls_kernel<<<nchunks, T>>>(logits, prefix_sum, out, total, num_segs);
}

// round 11
// speedup vs baseline: 1.8696x; 1.8696x over previous
#include <cuda_runtime.h>
#include <cstdint>

// Round 11: R9 structure (block-per-segment, fused sum(exp)+write, L1 re-read)
// made PERSISTENT with a dynamic segment work queue:
//  - grid = 148*16 blocks of 128 thr (one resident wave), segments pulled via
//    atomicAdd counter -> dynamic load balance kills wave/skew tail
//  - 4-deep batched float4 loads, no max pass, streaming stores
//  - packed f32x2 subtract in pass 2

#define T 128
#define NW (T / 32)
#define GRID (148 * 16)

__device__ int g_next;

__global__ void reset_kernel() { g_next = 0; }

__device__ __forceinline__ float warp_sum(float v) {
    #pragma unroll
    for (int o = 16; o > 0; o >>= 1)
        v += __shfl_xor_sync(0xFFFFFFFFu, v, o);
    return v;
}

__device__ __forceinline__ float4 sub_lse4(float4 v, uint64_t nls2) {
    // (v.x,v.y)+(-lse,-lse), (v.z,v.w)+(-lse,-lse) via packed f32x2
    uint64_t a, b;
    asm("mov.b64 %0, {%1, %2};" : "=l"(a) : "f"(v.x), "f"(v.y));
    asm("mov.b64 %0, {%1, %2};" : "=l"(b) : "f"(v.z), "f"(v.w));
    uint64_t ra, rb;
    asm("add.rn.f32x2 %0, %1, %2;" : "=l"(ra) : "l"(a), "l"(nls2));
    asm("add.rn.f32x2 %0, %1, %2;" : "=l"(rb) : "l"(b), "l"(nls2));
    float4 r;
    asm("mov.b64 {%0, %1}, %2;" : "=f"(r.x), "=f"(r.y) : "l"(ra));
    asm("mov.b64 {%0, %1}, %2;" : "=f"(r.z), "=f"(r.w) : "l"(rb));
    return r;
}

__global__ void __launch_bounds__(T)
jagged_log_softmax_kernel(const float* __restrict__ logits,
                          const int* __restrict__ prefix_sum,
                          float* __restrict__ out,
                          int nseg) {
    __shared__ float sm[NW];
    __shared__ float s_lse;
    __shared__ int   s_seg;

    const int tid  = threadIdx.x;
    const int lane = tid & 31;
    const int warp = tid >> 5;

    const float4* __restrict__ logits4 = (const float4*)logits;
    const int STEP = T * 4;

    for (;;) {
        if (tid == 0) s_seg = atomicAdd(&g_next, 1);
        __syncthreads();
        const int seg = s_seg;
        if (seg >= nseg) return;
        __syncthreads();            // s_seg safe to overwrite next iter

        const int start = (seg == 0) ? 0 : __ldg(&prefix_sum[seg - 1]);
        const int end   = __ldg(&prefix_sum[seg]);
        if (start >= end) continue;

        int astart = (start + 3) & ~3; if (astart > end) astart = end;
        int aend   = end & ~3;         if (aend < astart) aend = astart;

        // ---- Pass 1: sum of exp(x), 4-deep batched loads ----
        float s = 0.0f;

        for (int i = start + tid; i < astart; i += T)
            s += __expf(__ldg(&logits[i]));

        int i = astart + tid * 4;
        for (; i + 3 * STEP < aend; i += 4 * STEP) {
            float4 v0 = __ldg(&logits4[(i           ) >> 2]);
            float4 v1 = __ldg(&logits4[(i +     STEP) >> 2]);
            float4 v2 = __ldg(&logits4[(i + 2 * STEP) >> 2]);
            float4 v3 = __ldg(&logits4[(i + 3 * STEP) >> 2]);
            s += __expf(v0.x) + __expf(v0.y) + __expf(v0.z) + __expf(v0.w);
            s += __expf(v1.x) + __expf(v1.y) + __expf(v1.z) + __expf(v1.w);
            s += __expf(v2.x) + __expf(v2.y) + __expf(v2.z) + __expf(v2.w);
            s += __expf(v3.x) + __expf(v3.y) + __expf(v3.z) + __expf(v3.w);
        }
        for (; i < aend; i += STEP) {
            float4 v = __ldg(&logits4[i >> 2]);
            s += __expf(v.x) + __expf(v.y) + __expf(v.z) + __expf(v.w);
        }
        for (int j = aend + tid; j < end; j += T)
            s += __expf(__ldg(&logits[j]));

        // ---- block reduce (4 warps) ----
        s = warp_sum(s);
        if (lane == 0) sm[warp] = s;
        __syncthreads();
        if (warp == 0) {
            float v = (lane < NW) ? sm[lane] : 0.0f;
            #pragma unroll
            for (int o = NW / 2; o > 0; o >>= 1)
                v += __shfl_xor_sync(0xFFFFFFFFu, v, o);
            if (lane == 0) s_lse = __logf(v);
        }
        __syncthreads();
        const float lse = s_lse;

        uint64_t nls2;
        {
            float nl = -lse;
            asm("mov.b64 %0, {%1, %2};" : "=l"(nls2) : "f"(nl), "f"(nl));
        }

        // ---- Pass 2: write (re-read hits L1; packed subtract; streaming) ----
        for (int j = start + tid; j < astart; j += T)
            __stcs(&out[j], __ldg(&logits[j]) - lse);

        i = astart + tid * 4;
        for (; i + 3 * STEP < aend; i += 4 * STEP) {
            float4 v0 = __ldg(&logits4[(i           ) >> 2]);
            float4 v1 = __ldg(&logits4[(i +     STEP) >> 2]);
            float4 v2 = __ldg(&logits4[(i + 2 * STEP) >> 2]);
            float4 v3 = __ldg(&logits4[(i + 3 * STEP) >> 2]);
            __stcs((float4*)&out[i           ], sub_lse4(v0, nls2));
            __stcs((float4*)&out[i +     STEP], sub_lse4(v1, nls2));
            __stcs((float4*)&out[i + 2 * STEP], sub_lse4(v2, nls2));
            __stcs((float4*)&out[i + 3 * STEP], sub_lse4(v3, nls2));
        }
        for (; i < aend; i += STEP) {
            float4 v = __ldg(&logits4[i >> 2]);
            __stcs((float4*)&out[i], sub_lse4(v, nls2));
        }
        for (int j = aend + tid; j < end; j += T)
            __stcs(&out[j], __ldg(&logits[j]) - lse);

        __syncthreads();            // all done with s_lse before next segment
    }
}

extern "C" void kernel_launch(void* const* d_in, const int* in_sizes, int n_in,
                              void* d_out, int out_size) {
    const float* logits     = (const float*)d_in[0];
    const int*   prefix_sum = (const int*)d_in[1];
    float*       out        = (float*)d_out;

    const int num_segs = in_sizes[1];
    reset_kernel<<<1, 1>>>();
    jagged_log_softmax_kernel<<<GRID, T>>>(logits, prefix_sum, out, num_segs);
}